// round 12
// baseline (speedup 1.0000x reference)
#include <cuda_runtime.h>
#include <cstdint>

#define BB 8
#define NN 102400          // points per batch
#define DD 64
#define KK 16
#define ITERS 5
#define ST 128             // points per subtile
#define SUBT (NN/ST)       // 800 subtiles per batch
#define GRID 444           // 3*148 -> one resident wave at 3 CTAs/SM
#define SLOTS (2*KK*DD + KK)   // 2064
#define SLOT4 (SLOTS/4)        // 516
#define NTH 256

#define XSTRIDE 68         // padded row stride (floats) for sX (4-bank skew per row)
#define ABSTR 516          // AB block stride per kslot (floats): conflict-free skew
#define ABSZ (4*ABSTR)     // 2064 floats

// ---------------- device scratch ----------------
__device__ float g_post[(size_t)BB*NN*KK];       // posteriors [b][n][k] (52.4 MB)
__device__ float g_part[(size_t)GRID*SLOTS];     // per-CTA partials (linear cta id)
__device__ float g_sum[BB*SLOTS];                // reduced per-batch stats

// ---------------- cta -> (batch, bid) mapping: batches 0-3 get 56 CTAs, 4-7 get 55 ----------------
__device__ __forceinline__ void cta_map(int id, int& b, int& bid, int& start, int& schb) {
    if (id < 224) { b = id / 56;            start = b * 56;             schb = 56; }
    else          { b = 4 + (id - 224) / 55; start = 224 + (b - 4) * 55; schb = 55; }
    bid = id - start;
}
__device__ __forceinline__ void batch_range(int b, int& start, int& schb) {
    if (b < 4) { start = b * 56;             schb = 56; }
    else       { start = 224 + (b - 4) * 55; schb = 55; }
}

// ---------------- packed f32x2 helpers ----------------
__device__ __forceinline__ unsigned long long f2fma(unsigned long long a, unsigned long long b, unsigned long long c) {
    unsigned long long d;
    asm("fma.rn.f32x2 %0, %1, %2, %3;" : "=l"(d) : "l"(a), "l"(b), "l"(c));
    return d;
}
__device__ __forceinline__ unsigned long long f2mul(unsigned long long a, unsigned long long b) {
    unsigned long long d;
    asm("mul.rn.f32x2 %0, %1, %2;" : "=l"(d) : "l"(a), "l"(b));
    return d;
}
__device__ __forceinline__ unsigned long long fpack2(float lo, float hi) {
    unsigned long long r;
    asm("mov.b64 %0, {%1, %2};" : "=l"(r) : "f"(lo), "f"(hi));
    return r;
}
__device__ __forceinline__ float2 funpack2(unsigned long long v) {
    float2 f;
    asm("mov.b64 {%0, %1}, %2;" : "=f"(f.x), "=f"(f.y) : "l"(v));
    return f;
}

// ---------------- cp.async ----------------
__device__ __forceinline__ void cp16(uint32_t saddr, const void* g) {
    asm volatile("cp.async.ca.shared.global [%0], [%1], 16;" :: "r"(saddr), "l"(g));
}
__device__ __forceinline__ void cp_commit() { asm volatile("cp.async.commit_group;"); }
template<int N> __device__ __forceinline__ void cp_wait() {
    asm volatile("cp.async.wait_group %0;" :: "n"(N));
}
__device__ __forceinline__ uint32_t s2u(const void* p) {
    return (uint32_t)__cvta_generic_to_shared(p);
}

// stage ST=128 points (2048 float4) into padded smem buffer
__device__ __forceinline__ void stage(uint32_t sbuf, const float* __restrict__ src, int tid) {
#pragma unroll
    for (int r = 0; r < 8; ++r) {
        int i = tid + r * NTH;               // 0..2047
        int p = i >> 4, j = i & 15;
        cp16(sbuf + (uint32_t)(p * 17 + j) * 16, src + (size_t)i * 4);
    }
}

// rebuild params from reduced stats (any address space) or init means, into skewed smem AB + C
__device__ __forceinline__ void rebuild_params_smem(int tid, const float* acc,
                                                    float* sAB, float* sC,
                                                    const float* mrow, int init) {
    const int k = tid >> 4, dg = tid & 15;
    float cs = 0.f, pi;
    if (init) {
        pi = 1.0f / KK;
    } else {
        cs = acc[2 * KK * DD + k];
        float csumall = 0.f;
#pragma unroll
        for (int j = 0; j < KK; ++j) csumall += acc[2 * KK * DD + j];
        pi = cs / csumall;
    }

    float plog = 0.f, pmmi = 0.f;
    float A[4], Bc[4];
#pragma unroll
    for (int t = 0; t < 4; ++t) {
        int d = dg * 4 + t;
        float m, var;
        if (init) {
            m = mrow[k * DD + d];
            var = 1.0f;                                     // COV_INIT
        } else {
            float sx  = acc[k * DD + d];
            float sx2 = acc[KK * DD + k * DD + d];
            m   = sx / (cs + 1e-7f);
            var = sx2 - 2.0f * m * sx + m * m * cs + 1e-6f;
        }
        float inv = 1.0f / (var + 1e-6f);
        plog += logf(6.283185307179586f * var);
        pmmi += m * m * inv;
        A[t]  = m * inv;
        Bc[t] = -0.5f * inv;
    }

    float* abk = sAB + (k >> 2) * ABSTR + (k & 3) * 128;
    *(float4*)(abk + dg * 8)     = make_float4(A[0], A[1], Bc[0], Bc[1]);
    *(float4*)(abk + dg * 8 + 4) = make_float4(A[2], A[3], Bc[2], Bc[3]);

#pragma unroll
    for (int o = 8; o >= 1; o >>= 1) {
        plog += __shfl_xor_sync(0xffffffffu, plog, o);
        pmmi += __shfl_xor_sync(0xffffffffu, pmmi, o);
    }
    if (dg == 0) sC[k] = logf(pi) - 0.5f * plog - 0.5f * pmmi;
}

// Register-tiled logits: thread computes 2 points x 4 clusters.
__device__ __forceinline__ void logits_tile2(const float* __restrict__ xrow0,   // point p0; p1 = p0 + 8 rows
                                             const float* __restrict__ abk,    // sAB + kslot*ABSTR
                                             unsigned long long acc[2][4]) {
#pragma unroll
    for (int pt = 0; pt < 2; ++pt)
#pragma unroll
        for (int kk = 0; kk < 4; ++kk) acc[pt][kk] = 0ull;

#pragma unroll
    for (int it = 0; it < 16; ++it) {
        ulonglong2 x0 = *(const ulonglong2*)(xrow0 + it * 4);
        ulonglong2 x1 = *(const ulonglong2*)(xrow0 + 8 * XSTRIDE + it * 4);
#pragma unroll
        for (int kk = 0; kk < 4; ++kk) {
            ulonglong2 ab0 = *(const ulonglong2*)(abk + kk * 128 + it * 8);      // {A01,B01}
            ulonglong2 ab1 = *(const ulonglong2*)(abk + kk * 128 + it * 8 + 4);  // {A23,B23}
            unsigned long long u;
            u = f2fma(x0.x, ab0.y, ab0.x); acc[0][kk] = f2fma(x0.x, u, acc[0][kk]);
            u = f2fma(x0.y, ab1.y, ab1.x); acc[0][kk] = f2fma(x0.y, u, acc[0][kk]);
            u = f2fma(x1.x, ab0.y, ab0.x); acc[1][kk] = f2fma(x1.x, u, acc[1][kk]);
            u = f2fma(x1.y, ab1.y, ab1.x); acc[1][kk] = f2fma(x1.y, u, acc[1][kk]);
        }
    }
}

// ---------------- k_logits: phase A (logits+softmax) -> g_post, cs partials ----------------
// SMEM: sAB[2064] | sC[16] | sX[128*68]   (43136 B, 3 CTAs/SM)
__global__ void __launch_bounds__(NTH, 3)
k_logits(const float* __restrict__ data, const float* __restrict__ means, int iter) {
    extern __shared__ float sm[];
    float* sAB = sm;
    float* sC  = sm + ABSZ;
    float* sX  = sm + ABSZ + 16;

    const int tid   = threadIdx.x;
    const int lane  = tid & 31;
    const int warp  = tid >> 5;
    const int pslot = lane & 7;
    const int kslot = lane >> 3;

    int b, bid, start, schb;
    cta_map(blockIdx.x, b, bid, start, schb);

    const int nsub = (SUBT - 1 - bid) / schb + 1;
    const float* xb = data + (size_t)b * NN * DD;
    float* pb = g_post + (size_t)b * NN * KK;
    const uint32_t uX = s2u(sX);

    // prologue: rebuild params from g_sum (or init means)
    if (iter == 0) rebuild_params_smem(tid, 0, sAB, sC, means + (size_t)b * KK * DD, 1);
    else           rebuild_params_smem(tid, g_sum + b * SLOTS, sAB, sC, 0, 0);

    float csum[4] = {0.f, 0.f, 0.f, 0.f};

    for (int j = 0; j < nsub; ++j) {
        const int st = bid + j * schb;
        stage(uX, xb + (size_t)st * ST * DD, tid);
        cp_commit();
        cp_wait<0>();
        __syncthreads();

        unsigned long long acc[2][4];
        logits_tile2(sX + (warp * 16 + pslot) * XSTRIDE, sAB + kslot * ABSTR, acc);

#pragma unroll
        for (int pt = 0; pt < 2; ++pt) {
            float l[4];
#pragma unroll
            for (int kk = 0; kk < 4; ++kk) {
                float2 f = funpack2(acc[pt][kk]);
                l[kk] = sC[kslot * 4 + kk] + f.x + f.y;
            }
            float mx = fmaxf(fmaxf(l[0], l[1]), fmaxf(l[2], l[3]));
            mx = fmaxf(mx, __shfl_xor_sync(0xffffffffu, mx, 8));
            mx = fmaxf(mx, __shfl_xor_sync(0xffffffffu, mx, 16));
            float e0 = __expf(l[0] - mx), e1 = __expf(l[1] - mx);
            float e2 = __expf(l[2] - mx), e3 = __expf(l[3] - mx);
            float ssum = (e0 + e1) + (e2 + e3);
            ssum += __shfl_xor_sync(0xffffffffu, ssum, 8);
            ssum += __shfl_xor_sync(0xffffffffu, ssum, 16);
            float inv = 1.f / ssum;
            e0 *= inv; e1 *= inv; e2 *= inv; e3 *= inv;
            csum[0] += e0; csum[1] += e1; csum[2] += e2; csum[3] += e3;
            int p = warp * 16 + pslot + pt * 8;
            float* og = pb + ((size_t)st * ST + p) * KK + kslot * 4;
            *(float4*)og = make_float4(e0, e1, e2, e3);
        }
        __syncthreads();   // sX reused as stage target next iteration
    }

    // ---- cs epilogue: reduce over pslot lanes, warps, write partial slots 2048.. ----
#pragma unroll
    for (int o = 1; o <= 4; o <<= 1) {
#pragma unroll
        for (int kk = 0; kk < 4; ++kk)
            csum[kk] += __shfl_xor_sync(0xffffffffu, csum[kk], o);
    }
    if (pslot == 0) {
#pragma unroll
        for (int kk = 0; kk < 4; ++kk)
            sX[warp * KK + kslot * 4 + kk] = csum[kk];
    }
    __syncthreads();
    if (tid < KK) {
        float v = 0.f;
#pragma unroll
        for (int w = 0; w < 8; ++w) v += sX[w * KK + tid];
        g_part[(size_t)blockIdx.x * SLOTS + 2 * KK * DD + tid] = v;
    }
}

// ---------------- k_stats: phase B (weighted moments) -> partials 0..2047 ----------------
// SMEM: sX[128*68] | sPost[128*16]   (43008 B, 3 CTAs/SM)
__global__ void __launch_bounds__(NTH, 3)
k_stats(const float* __restrict__ data) {
    extern __shared__ float sm[];
    float* sX    = sm;
    float* sPost = sm + ST * XSTRIDE;

    const int tid = threadIdx.x;
    const int kg  = tid >> 6;
    const int rep = (tid >> 4) & 3;
    const int dg  = tid & 15;

    int b, bid, start, schb;
    cta_map(blockIdx.x, b, bid, start, schb);

    const int nsub = (SUBT - 1 - bid) / schb + 1;
    const float* xb = data + (size_t)b * NN * DD;
    const float* pb = g_post + (size_t)b * NN * KK;
    const uint32_t uX = s2u(sX), uP = s2u(sPost);

    unsigned long long sacc[4][2], qacc[4][2];
#pragma unroll
    for (int kk = 0; kk < 4; ++kk) {
        sacc[kk][0] = sacc[kk][1] = 0ull;
        qacc[kk][0] = qacc[kk][1] = 0ull;
    }

    for (int j = 0; j < nsub; ++j) {
        const int st = bid + j * schb;
        stage(uX, xb + (size_t)st * ST * DD, tid);
        {
            const float* ps = pb + (size_t)st * ST * KK;
#pragma unroll
            for (int r = 0; r < 2; ++r) {
                int i = tid + r * NTH;           // 0..511 float4
                cp16(uP + (uint32_t)i * 16, ps + (size_t)i * 4);
            }
        }
        cp_commit();
        cp_wait<0>();
        __syncthreads();

#pragma unroll 8
        for (int i = 0; i < ST / 4; ++i) {
            int n = i * 4 + rep;
            float4 pv = *(const float4*)(sPost + n * KK + kg * 4);
            ulonglong2 xv = *(const ulonglong2*)(sX + n * XSTRIDE + dg * 4);
            unsigned long long x2a = f2mul(xv.x, xv.x);
            unsigned long long x2b = f2mul(xv.y, xv.y);
#pragma unroll
            for (int kk = 0; kk < 4; ++kk) {
                float pp0 = (&pv.x)[kk];
                unsigned long long pp = fpack2(pp0, pp0);
                sacc[kk][0] = f2fma(pp, xv.x, sacc[kk][0]);
                sacc[kk][1] = f2fma(pp, xv.y, sacc[kk][1]);
                qacc[kk][0] = f2fma(pp, x2a, qacc[kk][0]);
                qacc[kk][1] = f2fma(pp, x2b, qacc[kk][1]);
            }
        }
        __syncthreads();   // sX/sPost reused as stage targets next iteration
    }

    // ---- reduce 4 point-replicas via smem, write partial ----
    const int NS = 2 * KK * DD;   // 2048
    float* sRed = sX;             // 4*NS = 8192 <= 8704
#pragma unroll
    for (int kk = 0; kk < 4; ++kk) {
        int k = kg * 4 + kk;
        float2 a0 = funpack2(sacc[kk][0]), a1 = funpack2(sacc[kk][1]);
        float2 b0 = funpack2(qacc[kk][0]), b1 = funpack2(qacc[kk][1]);
        *(float4*)(sRed + rep * NS + k * DD + dg * 4)           = make_float4(a0.x, a0.y, a1.x, a1.y);
        *(float4*)(sRed + rep * NS + KK * DD + k * DD + dg * 4) = make_float4(b0.x, b0.y, b1.x, b1.y);
    }
    __syncthreads();

    float* dst = g_part + (size_t)blockIdx.x * SLOTS;
    for (int i = tid; i < NS; i += NTH)
        dst[i] = (sRed[i] + sRed[NS + i]) + (sRed[2 * NS + i] + sRed[3 * NS + i]);
}

// ---------------- k_reduce: per-batch partial reduction -> g_sum ----------------
__global__ void k_reduce() {
    const int b = blockIdx.y;
    const int s4 = blockIdx.x * NTH + threadIdx.x;
    if (s4 >= SLOT4) return;
    int start, schb;
    batch_range(b, start, schb);
    const float* base = g_part + (size_t)start * SLOTS + s4 * 4;
    float4 v = make_float4(0.f, 0.f, 0.f, 0.f);
#pragma unroll 4
    for (int c = 0; c < schb; ++c) {
        float4 t = *(const float4*)(base + (size_t)c * SLOTS);
        v.x += t.x; v.y += t.y; v.z += t.z; v.w += t.w;
    }
    *(float4*)(g_sum + b * SLOTS + s4 * 4) = v;
}

// ---------------- k_final: prologue params + logits -> sigmoid ----------------
// SMEM: sAB[2064] | sC[16] | sX[128*68]
__global__ void __launch_bounds__(NTH, 3)
k_final(const float* __restrict__ data, const float* __restrict__ scale,
        const float* __restrict__ bias, float* __restrict__ out) {
    extern __shared__ float sm[];
    float* sAB = sm;
    float* sC  = sm + ABSZ;
    float* sX  = sm + ABSZ + 16;

    const int tid   = threadIdx.x;
    const int lane  = tid & 31;
    const int warp  = tid >> 5;
    const int pslot = lane & 7;
    const int kslot = lane >> 3;

    int b, bid, start, schb;
    cta_map(blockIdx.x, b, bid, start, schb);

    const int nsub = (SUBT - 1 - bid) / schb + 1;
    const float* xb = data + (size_t)b * NN * DD;
    const uint32_t uX = s2u(sX);

    rebuild_params_smem(tid, g_sum + b * SLOTS, sAB, sC, 0, 0);
    const float sc = scale[0], bs = bias[0];

    for (int j = 0; j < nsub; ++j) {
        const int st = bid + j * schb;
        stage(uX, xb + (size_t)st * ST * DD, tid);
        cp_commit();
        cp_wait<0>();
        __syncthreads();

        unsigned long long acc[2][4];
        logits_tile2(sX + (warp * 16 + pslot) * XSTRIDE, sAB + kslot * ABSTR, acc);

#pragma unroll
        for (int pt = 0; pt < 2; ++pt) {
            float o[4];
#pragma unroll
            for (int kk = 0; kk < 4; ++kk) {
                float2 f = funpack2(acc[pt][kk]);
                float z = (sC[kslot * 4 + kk] + f.x + f.y) * sc + bs;
                float e = __expf(-fabsf(z));
                float q = e / (1.f + e);
                o[kk] = (z >= 0.f) ? (1.f - q) : q;
            }
            int p = warp * 16 + pslot + pt * 8;
            float* og = out + ((size_t)b * NN + (size_t)st * ST + p) * KK + kslot * 4;
            *(float4*)og = make_float4(o[0], o[1], o[2], o[3]);
        }
        __syncthreads();   // sX reused as stage target next iteration
    }
}

// ---------------- host launcher (graph-capturable) ----------------
extern "C" void kernel_launch(void* const* d_in, const int* in_sizes, int n_in,
                              void* d_out, int out_size) {
    const float* data  = (const float*)d_in[0];
    const float* means = (const float*)d_in[1];
    const float* scale = (const float*)d_in[2];
    const float* bias  = (const float*)d_in[3];
    float* out = (float*)d_out;

    const int smem_l = (ABSZ + 16 + ST * XSTRIDE) * 4;   // 43136
    const int smem_s = (ST * XSTRIDE + ST * KK) * 4;     // 43008
    cudaFuncSetAttribute(k_logits, cudaFuncAttributeMaxDynamicSharedMemorySize, smem_l);
    cudaFuncSetAttribute(k_stats,  cudaFuncAttributeMaxDynamicSharedMemorySize, smem_s);
    cudaFuncSetAttribute(k_final,  cudaFuncAttributeMaxDynamicSharedMemorySize, smem_l);

    dim3 gr((SLOT4 + NTH - 1) / NTH, BB);   // (3, 8)

    for (int i = 0; i < ITERS; ++i) {
        k_logits<<<GRID, NTH, smem_l>>>(data, means, i);
        k_stats<<<GRID, NTH, smem_s>>>(data);
        k_reduce<<<gr, NTH>>>();
    }
    k_final<<<GRID, NTH, smem_l>>>(data, scale, bias, out);
}

// round 13
// speedup vs baseline: 1.0981x; 1.0981x over previous
#include <cuda_runtime.h>
#include <cstdint>

#define BB 8
#define NN 102400          // points per batch
#define DD 64
#define KK 16
#define ITERS 5
#define ST 128             // points per subtile
#define SUBT (NN/ST)       // 800 subtiles per batch
#define SCH 37             // estep CTAs per batch; 37*8 = 296 = 2*148 -> one wave at 2/SM
#define FGRID 444          // k_final: 3*148 -> one wave at 3/SM
#define SLOTS (2*KK*DD + KK)   // 2064
#define SLOT4 (SLOTS/4)        // 516
#define NTH 256

#define XSTRIDE 68         // padded row stride (floats) for sX (4-bank skew per row)
#define PSTR 20            // padded row stride for posteriors (sPostT: 2560 >= SLOTS)
#define ABSTR 260          // AB block stride per kslot-pair (floats): 4-bank skew, conflict-free
#define ABSZ (8*ABSTR)     // 2080 floats

// ---------------- device scratch ----------------
__device__ float g_part[2][(size_t)BB*SCH*SLOTS];   // parity double-buffered partials

// ---------------- packed f32x2 helpers ----------------
__device__ __forceinline__ unsigned long long f2fma(unsigned long long a, unsigned long long b, unsigned long long c) {
    unsigned long long d;
    asm("fma.rn.f32x2 %0, %1, %2, %3;" : "=l"(d) : "l"(a), "l"(b), "l"(c));
    return d;
}
__device__ __forceinline__ unsigned long long f2mul(unsigned long long a, unsigned long long b) {
    unsigned long long d;
    asm("mul.rn.f32x2 %0, %1, %2;" : "=l"(d) : "l"(a), "l"(b));
    return d;
}
__device__ __forceinline__ unsigned long long fpack2(float lo, float hi) {
    unsigned long long r;
    asm("mov.b64 %0, {%1, %2};" : "=l"(r) : "f"(lo), "f"(hi));
    return r;
}
__device__ __forceinline__ float2 funpack2(unsigned long long v) {
    float2 f;
    asm("mov.b64 {%0, %1}, %2;" : "=f"(f.x), "=f"(f.y) : "l"(v));
    return f;
}

// ---------------- cp.async ----------------
__device__ __forceinline__ void cp16(uint32_t saddr, const void* g) {
    asm volatile("cp.async.ca.shared.global [%0], [%1], 16;" :: "r"(saddr), "l"(g));
}
__device__ __forceinline__ void cp_commit() { asm volatile("cp.async.commit_group;"); }
template<int N> __device__ __forceinline__ void cp_wait() {
    asm volatile("cp.async.wait_group %0;" :: "n"(N));
}
__device__ __forceinline__ uint32_t s2u(const void* p) {
    return (uint32_t)__cvta_generic_to_shared(p);
}

// stage ST=128 points (2048 float4) into padded smem buffer
__device__ __forceinline__ void stage(uint32_t sbuf, const float* __restrict__ src, int tid) {
#pragma unroll
    for (int r = 0; r < 8; ++r) {
        int i = tid + r * NTH;               // 0..2047
        int p = i >> 4, j = i & 15;
        cp16(sbuf + (uint32_t)(p * 17 + j) * 16, src + (size_t)i * 4);
    }
}

// rebuild params from reduced stats (smem) or init means, into skewed smem AB + C
// layout: cluster k at (k>>1)*ABSTR + (k&1)*128, inner per-dg {A01,B01,A23,B23}
__device__ __forceinline__ void rebuild_params_smem(int tid, const float* acc,
                                                    float* sAB, float* sC,
                                                    const float* mrow, int init) {
    const int k = tid >> 4, dg = tid & 15;
    float cs = 0.f, pi;
    if (init) {
        pi = 1.0f / KK;
    } else {
        cs = acc[2 * KK * DD + k];
        float csumall = 0.f;
#pragma unroll
        for (int j = 0; j < KK; ++j) csumall += acc[2 * KK * DD + j];
        pi = cs / csumall;
    }

    float plog = 0.f, pmmi = 0.f;
    float A[4], Bc[4];
#pragma unroll
    for (int t = 0; t < 4; ++t) {
        int d = dg * 4 + t;
        float m, var;
        if (init) {
            m = mrow[k * DD + d];
            var = 1.0f;                                     // COV_INIT
        } else {
            float sx  = acc[k * DD + d];
            float sx2 = acc[KK * DD + k * DD + d];
            m   = sx / (cs + 1e-7f);
            var = sx2 - 2.0f * m * sx + m * m * cs + 1e-6f;
        }
        float inv = 1.0f / (var + 1e-6f);
        plog += logf(6.283185307179586f * var);
        pmmi += m * m * inv;
        A[t]  = m * inv;
        Bc[t] = -0.5f * inv;
    }

    float* abk = sAB + (k >> 1) * ABSTR + (k & 1) * 128;
    *(float4*)(abk + dg * 8)     = make_float4(A[0], A[1], Bc[0], Bc[1]);
    *(float4*)(abk + dg * 8 + 4) = make_float4(A[2], A[3], Bc[2], Bc[3]);

#pragma unroll
    for (int o = 8; o >= 1; o >>= 1) {
        plog += __shfl_xor_sync(0xffffffffu, plog, o);
        pmmi += __shfl_xor_sync(0xffffffffu, pmmi, o);
    }
    if (dg == 0) sC[k] = logf(pi) - 0.5f * plog - 0.5f * pmmi;
}

// vectorized prologue reduction: sum 37 per-CTA partials into smem scratch
__device__ __forceinline__ void reduce_partials(const float* __restrict__ base,
                                                float* __restrict__ accs, int tid) {
    for (int s = tid; s < SLOT4; s += NTH) {
        float4 v = make_float4(0.f, 0.f, 0.f, 0.f);
#pragma unroll 4
        for (int c = 0; c < SCH; ++c) {
            float4 t = *(const float4*)(base + (size_t)c * SLOTS + s * 4);
            v.x += t.x; v.y += t.y; v.z += t.z; v.w += t.w;
        }
        *(float4*)(accs + s * 4) = v;
    }
}

// Register-tiled logits: thread computes 4 points x 2 clusters (conflict-free skewed AB).
// xr = sX + p0*XSTRIDE; points at rows p0, p0+4, p0+8, p0+12. abk = sAB + kslot*ABSTR.
__device__ __forceinline__ void logits_tile42(const float* __restrict__ xr,
                                              const float* __restrict__ abk,
                                              unsigned long long acc[4][2]) {
#pragma unroll
    for (int pt = 0; pt < 4; ++pt) { acc[pt][0] = 0ull; acc[pt][1] = 0ull; }

#pragma unroll
    for (int it = 0; it < 16; ++it) {
        ulonglong2 x[4];
#pragma unroll
        for (int pt = 0; pt < 4; ++pt)
            x[pt] = *(const ulonglong2*)(xr + pt * 4 * XSTRIDE + it * 4);
#pragma unroll
        for (int kk = 0; kk < 2; ++kk) {
            ulonglong2 ab0 = *(const ulonglong2*)(abk + kk * 128 + it * 8);      // {A01,B01}
            ulonglong2 ab1 = *(const ulonglong2*)(abk + kk * 128 + it * 8 + 4);  // {A23,B23}
#pragma unroll
            for (int pt = 0; pt < 4; ++pt) {
                unsigned long long u;
                u = f2fma(x[pt].x, ab0.y, ab0.x); acc[pt][kk] = f2fma(x[pt].x, u, acc[pt][kk]);
                u = f2fma(x[pt].y, ab1.y, ab1.x); acc[pt][kk] = f2fma(x[pt].y, u, acc[pt][kk]);
            }
        }
    }
}

// ---------------- E-step (persistent CTA; params rebuilt in prologue) ----------------
// SMEM (floats): sAB[2080] | sC[16] | sX0[128*68] | sX1[128*68] | sPostT[128*20]
__global__ void __launch_bounds__(NTH, 2)
k_estep(const float* __restrict__ data, const float* __restrict__ means, int iter) {
    extern __shared__ float sm[];
    float* sAB    = sm;
    float* sC     = sm + ABSZ;
    float* sX0    = sm + ABSZ + 16;
    float* sX1    = sX0 + ST * XSTRIDE;
    float* sPostT = sX1 + ST * XSTRIDE;

    const int tid   = threadIdx.x;
    const int lane  = tid & 31;
    const int warp  = tid >> 5;
    const int pslot = lane & 3;         // 0..3
    const int kslot = lane >> 2;        // 0..7, 2 clusters each
    const int bid   = blockIdx.x;       // 0..36
    const int b     = blockIdx.y;

    // phase-B mapping: clusters kg*4..+3, dims dg*4..+3, points n = 4i+rep
    const int kg  = tid >> 6;
    const int rep = (tid >> 4) & 3;
    const int dg  = tid & 15;

    const int nsub = (SUBT - 1 - bid) / SCH + 1;    // 22 or 21
    const float* xb = data + (size_t)b * NN * DD;
    const uint32_t uX0 = s2u(sX0), uX1 = s2u(sX1);

    // prologue: prefetch subtile bid; reduce prev partials + rebuild params (overlapped)
    stage(uX0, xb + (size_t)bid * ST * DD, tid);
    cp_commit();
    if (iter == 0) {
        rebuild_params_smem(tid, 0, sAB, sC, means + (size_t)b * KK * DD, 1);
    } else {
        reduce_partials(g_part[(iter - 1) & 1] + (size_t)b * SCH * SLOTS, sPostT, tid);
        __syncthreads();
        rebuild_params_smem(tid, sPostT, sAB, sC, 0, 0);
    }

    // persistent accumulators (whole CTA workload)
    unsigned long long sacc[4][2], qacc[4][2];
    float csum[2] = {0.f, 0.f};
#pragma unroll
    for (int kk = 0; kk < 4; ++kk) {
        sacc[kk][0] = sacc[kk][1] = 0ull;
        qacc[kk][0] = qacc[kk][1] = 0ull;
    }

    for (int j = 0; j < nsub; ++j) {
        float* sX = (j & 1) ? sX1 : sX0;
        if (j + 1 < nsub) {
            stage((j & 1) ? uX0 : uX1, xb + (size_t)(bid + (j + 1) * SCH) * ST * DD, tid);
            cp_commit();
            cp_wait<1>();
        } else {
            cp_wait<0>();
        }
        __syncthreads();

        // ---- phase A: logits + softmax (4 points x 2 clusters per thread) ----
        unsigned long long acc[4][2];
        logits_tile42(sX + (warp * 16 + pslot) * XSTRIDE, sAB + kslot * ABSTR, acc);

#pragma unroll
        for (int pt = 0; pt < 4; ++pt) {
            float2 f0 = funpack2(acc[pt][0]);
            float2 f1 = funpack2(acc[pt][1]);
            float l0 = sC[kslot * 2]     + f0.x + f0.y;
            float l1 = sC[kslot * 2 + 1] + f1.x + f1.y;
            float mx = fmaxf(l0, l1);
            mx = fmaxf(mx, __shfl_xor_sync(0xffffffffu, mx, 4));
            mx = fmaxf(mx, __shfl_xor_sync(0xffffffffu, mx, 8));
            mx = fmaxf(mx, __shfl_xor_sync(0xffffffffu, mx, 16));
            float e0 = __expf(l0 - mx), e1 = __expf(l1 - mx);
            float ssum = e0 + e1;
            ssum += __shfl_xor_sync(0xffffffffu, ssum, 4);
            ssum += __shfl_xor_sync(0xffffffffu, ssum, 8);
            ssum += __shfl_xor_sync(0xffffffffu, ssum, 16);
            float inv = 1.f / ssum;
            e0 *= inv; e1 *= inv;
            csum[0] += e0; csum[1] += e1;
            int p = warp * 16 + pslot + pt * 4;
            *(float2*)(sPostT + p * PSTR + kslot * 2) = make_float2(e0, e1);
        }
        __syncthreads();

        // ---- phase B: accumulate sx, sx2 (4k x 4d tile, x^2 hoisted) ----
#pragma unroll 8
        for (int i = 0; i < ST / 4; ++i) {
            int n = i * 4 + rep;
            float4 pv = *(const float4*)(sPostT + n * PSTR + kg * 4);
            ulonglong2 xv = *(const ulonglong2*)(sX + n * XSTRIDE + dg * 4);
            unsigned long long x2a = f2mul(xv.x, xv.x);
            unsigned long long x2b = f2mul(xv.y, xv.y);
#pragma unroll
            for (int kk = 0; kk < 4; ++kk) {
                float pp0 = (&pv.x)[kk];
                unsigned long long pp = fpack2(pp0, pp0);
                sacc[kk][0] = f2fma(pp, xv.x, sacc[kk][0]);
                sacc[kk][1] = f2fma(pp, xv.y, sacc[kk][1]);
                qacc[kk][0] = f2fma(pp, x2a, qacc[kk][0]);
                qacc[kk][1] = f2fma(pp, x2b, qacc[kk][1]);
            }
        }
        __syncthreads();   // sX is prefetch target next iteration; sPostT rewritten
    }

    // ---- csum: reduce over the 4 pslot lanes of each kslot group ----
#pragma unroll
    for (int o = 1; o <= 2; o <<= 1) {
        csum[0] += __shfl_xor_sync(0xffffffffu, csum[0], o);
        csum[1] += __shfl_xor_sync(0xffffffffu, csum[1], o);
    }
    if (pslot == 0) {
        sPostT[warp * KK + kslot * 2]     = csum[0];   // per-warp cs staging
        sPostT[warp * KK + kslot * 2 + 1] = csum[1];
    }

    // ---- reduce 4 point-replicas of sacc/qacc via smem (sRed spans sX0+sX1) ----
    const int NS = 2 * KK * DD;   // 2048
    float* sRed = sX0;            // 4*NS = 8192 floats <= 17408
#pragma unroll
    for (int kk = 0; kk < 4; ++kk) {
        int k = kg * 4 + kk;
        float2 a0 = funpack2(sacc[kk][0]), a1 = funpack2(sacc[kk][1]);
        float2 b0 = funpack2(qacc[kk][0]), b1 = funpack2(qacc[kk][1]);
        *(float4*)(sRed + rep * NS + k * DD + dg * 4)           = make_float4(a0.x, a0.y, a1.x, a1.y);
        *(float4*)(sRed + rep * NS + KK * DD + k * DD + dg * 4) = make_float4(b0.x, b0.y, b1.x, b1.y);
    }
    __syncthreads();

    float* dst = g_part[iter & 1] + ((size_t)(b * SCH + bid)) * SLOTS;
    for (int i = tid; i < NS; i += NTH)
        dst[i] = (sRed[i] + sRed[NS + i]) + (sRed[2 * NS + i] + sRed[3 * NS + i]);
    if (tid < KK) {
        float v = 0.f;
#pragma unroll
        for (int w = 0; w < 8; ++w) v += sPostT[w * KK + tid];
        dst[NS + tid] = v;
    }
}

// ---------------- Final (flat 444 grid, 3 CTAs/SM): prologue params + logits -> sigmoid ----------------
// SMEM: sAB[2080] | sC[16] | sX[128*68]
__global__ void __launch_bounds__(NTH, 3)
k_final(const float* __restrict__ data, const float* __restrict__ scale,
        const float* __restrict__ bias, float* __restrict__ out) {
    extern __shared__ float sm[];
    float* sAB = sm;
    float* sC  = sm + ABSZ;
    float* sX  = sm + ABSZ + 16;

    const int tid   = threadIdx.x;
    const int lane  = tid & 31;
    const int warp  = tid >> 5;
    const int pslot = lane & 3;
    const int kslot = lane >> 2;

    // flat cta -> (batch, bid): batches 0-3 get 56 CTAs, 4-7 get 55
    int id = blockIdx.x, b, bid, schb;
    if (id < 224) { b = id / 56;             bid = id - b * 56;             schb = 56; }
    else          { b = 4 + (id - 224) / 55; bid = (id - 224) - (b - 4) * 55; schb = 55; }

    const int nsub = (SUBT - 1 - bid) / schb + 1;
    const float* xb = data + (size_t)b * NN * DD;
    const uint32_t uX = s2u(sX);

    // prologue: reduce final partials + rebuild params (sX as scratch, pre-staging)
    reduce_partials(g_part[(ITERS - 1) & 1] + (size_t)b * SCH * SLOTS, sX, tid);
    __syncthreads();
    rebuild_params_smem(tid, sX, sAB, sC, 0, 0);
    __syncthreads();

    const float sc = scale[0], bs = bias[0];

    for (int j = 0; j < nsub; ++j) {
        const int st = bid + j * schb;
        stage(uX, xb + (size_t)st * ST * DD, tid);
        cp_commit();
        cp_wait<0>();
        __syncthreads();

        unsigned long long acc[4][2];
        logits_tile42(sX + (warp * 16 + pslot) * XSTRIDE, sAB + kslot * ABSTR, acc);

#pragma unroll
        for (int pt = 0; pt < 4; ++pt) {
            float o[2];
#pragma unroll
            for (int kk = 0; kk < 2; ++kk) {
                float2 f = funpack2(acc[pt][kk]);
                float z = (sC[kslot * 2 + kk] + f.x + f.y) * sc + bs;
                float e = __expf(-fabsf(z));
                float q = e / (1.f + e);
                o[kk] = (z >= 0.f) ? (1.f - q) : q;
            }
            int p = warp * 16 + pslot + pt * 4;
            float* og = out + ((size_t)b * NN + (size_t)st * ST + p) * KK + kslot * 2;
            *(float2*)og = make_float2(o[0], o[1]);
        }
        __syncthreads();   // sX reused as stage target next iteration
    }
}

// ---------------- host launcher (graph-capturable) ----------------
extern "C" void kernel_launch(void* const* d_in, const int* in_sizes, int n_in,
                              void* d_out, int out_size) {
    const float* data  = (const float*)d_in[0];
    const float* means = (const float*)d_in[1];
    const float* scale = (const float*)d_in[2];
    const float* bias  = (const float*)d_in[3];
    float* out = (float*)d_out;

    const int smem_e = (ABSZ + 16 + 2 * ST * XSTRIDE + ST * PSTR) * 4;   // 88256
    const int smem_f = (ABSZ + 16 + ST * XSTRIDE) * 4;                   // 43200
    cudaFuncSetAttribute(k_estep, cudaFuncAttributeMaxDynamicSharedMemorySize, smem_e);
    cudaFuncSetAttribute(k_final, cudaFuncAttributeMaxDynamicSharedMemorySize, smem_f);

    dim3 ge(SCH, BB);                           // 296 CTAs = one full resident wave at 2/SM

    for (int i = 0; i < ITERS; ++i)
        k_estep<<<ge, NTH, smem_e>>>(data, means, i);   // params rebuilt in prologue
    k_final<<<FGRID, NTH, smem_f>>>(data, scale, bias, out);
}

// round 14
// speedup vs baseline: 1.1259x; 1.0253x over previous
#include <cuda_runtime.h>
#include <cstdint>

#define BB 8
#define NN 102400          // points per batch
#define DD 64
#define KK 16
#define ITERS 5
#define ST 128             // points per subtile
#define SUBT (NN/ST)       // 800 subtiles per batch
#define SCH 37             // estep CTAs per batch; 37*8 = 296 = 2*148 -> one wave at 2/SM
#define FGRID 444          // k_final: 3*148 -> one wave at 3/SM
#define SLOTS (2*KK*DD + KK)   // 2064
#define SLOT4 (SLOTS/4)        // 516
#define NTH 256

#define XSTRIDE 68         // padded row stride (floats) for sX (4-bank skew per row)
#define PSTR 20            // padded row stride for posteriors (sPostT: 2560 >= SLOTS)
#define ABSTR 516          // AB block stride per kslot (floats): 4-bank skew, conflict-free
#define ABSZ (4*ABSTR)     // 2064 floats

// ---------------- device scratch ----------------
__device__ float g_part[2][(size_t)BB*SCH*SLOTS];   // parity double-buffered partials

// ---------------- packed f32x2 helpers ----------------
__device__ __forceinline__ unsigned long long f2fma(unsigned long long a, unsigned long long b, unsigned long long c) {
    unsigned long long d;
    asm("fma.rn.f32x2 %0, %1, %2, %3;" : "=l"(d) : "l"(a), "l"(b), "l"(c));
    return d;
}
__device__ __forceinline__ unsigned long long f2mul(unsigned long long a, unsigned long long b) {
    unsigned long long d;
    asm("mul.rn.f32x2 %0, %1, %2;" : "=l"(d) : "l"(a), "l"(b));
    return d;
}
__device__ __forceinline__ unsigned long long fpack2(float lo, float hi) {
    unsigned long long r;
    asm("mov.b64 %0, {%1, %2};" : "=l"(r) : "f"(lo), "f"(hi));
    return r;
}
__device__ __forceinline__ float2 funpack2(unsigned long long v) {
    float2 f;
    asm("mov.b64 {%0, %1}, %2;" : "=f"(f.x), "=f"(f.y) : "l"(v));
    return f;
}

// ---------------- cp.async ----------------
__device__ __forceinline__ void cp16(uint32_t saddr, const void* g) {
    asm volatile("cp.async.ca.shared.global [%0], [%1], 16;" :: "r"(saddr), "l"(g));
}
__device__ __forceinline__ void cp_commit() { asm volatile("cp.async.commit_group;"); }
template<int N> __device__ __forceinline__ void cp_wait() {
    asm volatile("cp.async.wait_group %0;" :: "n"(N));
}
__device__ __forceinline__ uint32_t s2u(const void* p) {
    return (uint32_t)__cvta_generic_to_shared(p);
}

// stage ST=128 points (2048 float4) into padded smem buffer
__device__ __forceinline__ void stage(uint32_t sbuf, const float* __restrict__ src, int tid) {
#pragma unroll
    for (int r = 0; r < 8; ++r) {
        int i = tid + r * NTH;               // 0..2047
        int p = i >> 4, j = i & 15;
        cp16(sbuf + (uint32_t)(p * 17 + j) * 16, src + (size_t)i * 4);
    }
}

// rebuild params from reduced stats (smem) or init means, into skewed smem AB + C
// layout: cluster k at (k>>2)*ABSTR + (k&3)*128, inner per-dg {A01,B01,A23,B23}
__device__ __forceinline__ void rebuild_params_smem(int tid, const float* acc,
                                                    float* sAB, float* sC,
                                                    const float* mrow, int init) {
    const int k = tid >> 4, dg = tid & 15;
    float cs = 0.f, pi;
    if (init) {
        pi = 1.0f / KK;
    } else {
        cs = acc[2 * KK * DD + k];
        float csumall = 0.f;
#pragma unroll
        for (int j = 0; j < KK; ++j) csumall += acc[2 * KK * DD + j];
        pi = cs / csumall;
    }

    float plog = 0.f, pmmi = 0.f;
    float A[4], Bc[4];
#pragma unroll
    for (int t = 0; t < 4; ++t) {
        int d = dg * 4 + t;
        float m, var;
        if (init) {
            m = mrow[k * DD + d];
            var = 1.0f;                                     // COV_INIT
        } else {
            float sx  = acc[k * DD + d];
            float sx2 = acc[KK * DD + k * DD + d];
            m   = sx / (cs + 1e-7f);
            var = sx2 - 2.0f * m * sx + m * m * cs + 1e-6f;
        }
        float inv = 1.0f / (var + 1e-6f);
        plog += logf(6.283185307179586f * var);
        pmmi += m * m * inv;
        A[t]  = m * inv;
        Bc[t] = -0.5f * inv;
    }

    float* abk = sAB + (k >> 2) * ABSTR + (k & 3) * 128;
    *(float4*)(abk + dg * 8)     = make_float4(A[0], A[1], Bc[0], Bc[1]);
    *(float4*)(abk + dg * 8 + 4) = make_float4(A[2], A[3], Bc[2], Bc[3]);

#pragma unroll
    for (int o = 8; o >= 1; o >>= 1) {
        plog += __shfl_xor_sync(0xffffffffu, plog, o);
        pmmi += __shfl_xor_sync(0xffffffffu, pmmi, o);
    }
    if (dg == 0) sC[k] = logf(pi) - 0.5f * plog - 0.5f * pmmi;
}

// vectorized prologue reduction: sum 37 per-CTA partials into smem scratch
__device__ __forceinline__ void reduce_partials(const float* __restrict__ base,
                                                float* __restrict__ accs, int tid) {
    for (int s = tid; s < SLOT4; s += NTH) {
        float4 v = make_float4(0.f, 0.f, 0.f, 0.f);
#pragma unroll 4
        for (int c = 0; c < SCH; ++c) {
            float4 t = *(const float4*)(base + (size_t)c * SLOTS + s * 4);
            v.x += t.x; v.y += t.y; v.z += t.z; v.w += t.w;
        }
        *(float4*)(accs + s * 4) = v;
    }
}

// Register-tiled logits: thread computes 2 points x 4 clusters.
__device__ __forceinline__ void logits_tile2(const float* __restrict__ xrow0,   // point p0; p1 = p0 + 8 rows
                                             const float* __restrict__ abk,    // sAB + kslot*ABSTR
                                             unsigned long long acc[2][4]) {
#pragma unroll
    for (int pt = 0; pt < 2; ++pt)
#pragma unroll
        for (int kk = 0; kk < 4; ++kk) acc[pt][kk] = 0ull;

#pragma unroll
    for (int it = 0; it < 16; ++it) {
        ulonglong2 x0 = *(const ulonglong2*)(xrow0 + it * 4);
        ulonglong2 x1 = *(const ulonglong2*)(xrow0 + 8 * XSTRIDE + it * 4);
#pragma unroll
        for (int kk = 0; kk < 4; ++kk) {
            ulonglong2 ab0 = *(const ulonglong2*)(abk + kk * 128 + it * 8);      // {A01,B01}
            ulonglong2 ab1 = *(const ulonglong2*)(abk + kk * 128 + it * 8 + 4);  // {A23,B23}
            unsigned long long u;
            u = f2fma(x0.x, ab0.y, ab0.x); acc[0][kk] = f2fma(x0.x, u, acc[0][kk]);
            u = f2fma(x0.y, ab1.y, ab1.x); acc[0][kk] = f2fma(x0.y, u, acc[0][kk]);
            u = f2fma(x1.x, ab0.y, ab0.x); acc[1][kk] = f2fma(x1.x, u, acc[1][kk]);
            u = f2fma(x1.y, ab1.y, ab1.x); acc[1][kk] = f2fma(x1.y, u, acc[1][kk]);
        }
    }
}

// ---------------- E-step (persistent CTA; params rebuilt in prologue) ----------------
// SMEM (floats): sAB[2064] | sC[16] | sX0[128*68] | sX1[128*68] | sPostT[128*20]
__global__ void __launch_bounds__(NTH, 2)
k_estep(const float* __restrict__ data, const float* __restrict__ means, int iter) {
    extern __shared__ float sm[];
    float* sAB    = sm;
    float* sC     = sm + ABSZ;
    float* sX0    = sm + ABSZ + 16;
    float* sX1    = sX0 + ST * XSTRIDE;
    float* sPostT = sX1 + ST * XSTRIDE;

    const int tid   = threadIdx.x;
    const int lane  = tid & 31;
    const int warp  = tid >> 5;
    const int pslot = lane & 7;
    const int kslot = lane >> 3;
    const int bid   = blockIdx.x;       // 0..36
    const int b     = blockIdx.y;

    // phase-B mapping: clusters kg*4..+3, dims dg*4..+3, points n = 4i+rep
    const int kg  = tid >> 6;
    const int rep = (tid >> 4) & 3;
    const int dg  = tid & 15;

    const int nsub = (SUBT - 1 - bid) / SCH + 1;    // 22 or 21
    const float* xb = data + (size_t)b * NN * DD;
    const uint32_t uX0 = s2u(sX0), uX1 = s2u(sX1);

    // prologue: prefetch subtile bid; reduce prev partials + rebuild params (overlapped)
    stage(uX0, xb + (size_t)bid * ST * DD, tid);
    cp_commit();
    if (iter == 0) {
        rebuild_params_smem(tid, 0, sAB, sC, means + (size_t)b * KK * DD, 1);
    } else {
        reduce_partials(g_part[(iter - 1) & 1] + (size_t)b * SCH * SLOTS, sPostT, tid);
        __syncthreads();
        rebuild_params_smem(tid, sPostT, sAB, sC, 0, 0);
    }

    // persistent accumulators (whole CTA workload)
    unsigned long long sacc[4][2], qacc[4][2];
    float csum[4];
#pragma unroll
    for (int kk = 0; kk < 4; ++kk) {
        sacc[kk][0] = sacc[kk][1] = 0ull;
        qacc[kk][0] = qacc[kk][1] = 0ull;
        csum[kk] = 0.f;
    }

    for (int j = 0; j < nsub; ++j) {
        float* sX = (j & 1) ? sX1 : sX0;
        if (j + 1 < nsub) {
            stage((j & 1) ? uX0 : uX1, xb + (size_t)(bid + (j + 1) * SCH) * ST * DD, tid);
            cp_commit();
            cp_wait<1>();
        } else {
            cp_wait<0>();
        }
        __syncthreads();

        // ---- phase A: logits + softmax (2 points x 4 clusters per thread) ----
        unsigned long long acc[2][4];
        logits_tile2(sX + (warp * 16 + pslot) * XSTRIDE, sAB + kslot * ABSTR, acc);

#pragma unroll
        for (int pt = 0; pt < 2; ++pt) {
            float l[4];
#pragma unroll
            for (int kk = 0; kk < 4; ++kk) {
                float2 f = funpack2(acc[pt][kk]);
                l[kk] = sC[kslot * 4 + kk] + f.x + f.y;
            }
            float mx = fmaxf(fmaxf(l[0], l[1]), fmaxf(l[2], l[3]));
            mx = fmaxf(mx, __shfl_xor_sync(0xffffffffu, mx, 8));
            mx = fmaxf(mx, __shfl_xor_sync(0xffffffffu, mx, 16));
            float e0 = __expf(l[0] - mx), e1 = __expf(l[1] - mx);
            float e2 = __expf(l[2] - mx), e3 = __expf(l[3] - mx);
            float ssum = (e0 + e1) + (e2 + e3);
            ssum += __shfl_xor_sync(0xffffffffu, ssum, 8);
            ssum += __shfl_xor_sync(0xffffffffu, ssum, 16);
            float inv = 1.f / ssum;
            e0 *= inv; e1 *= inv; e2 *= inv; e3 *= inv;
            csum[0] += e0; csum[1] += e1; csum[2] += e2; csum[3] += e3;
            int p = warp * 16 + pslot + pt * 8;
            *(float4*)(sPostT + p * PSTR + kslot * 4) = make_float4(e0, e1, e2, e3);
        }
        __syncthreads();

        // ---- phase B: accumulate sx, sx2 (4k x 4d tile, x^2 hoisted) ----
#pragma unroll 8
        for (int i = 0; i < ST / 4; ++i) {
            int n = i * 4 + rep;
            float4 pv = *(const float4*)(sPostT + n * PSTR + kg * 4);
            ulonglong2 xv = *(const ulonglong2*)(sX + n * XSTRIDE + dg * 4);
            unsigned long long x2a = f2mul(xv.x, xv.x);
            unsigned long long x2b = f2mul(xv.y, xv.y);
#pragma unroll
            for (int kk = 0; kk < 4; ++kk) {
                float pp0 = (&pv.x)[kk];
                unsigned long long pp = fpack2(pp0, pp0);
                sacc[kk][0] = f2fma(pp, xv.x, sacc[kk][0]);
                sacc[kk][1] = f2fma(pp, xv.y, sacc[kk][1]);
                qacc[kk][0] = f2fma(pp, x2a, qacc[kk][0]);
                qacc[kk][1] = f2fma(pp, x2b, qacc[kk][1]);
            }
        }
        __syncthreads();   // sX is prefetch target next iteration; sPostT rewritten
    }

    // ---- csum: reduce over the 8 pslot lanes of each kslot group ----
#pragma unroll
    for (int o = 1; o <= 4; o <<= 1) {
#pragma unroll
        for (int kk = 0; kk < 4; ++kk)
            csum[kk] += __shfl_xor_sync(0xffffffffu, csum[kk], o);
    }
    if (pslot == 0) {
#pragma unroll
        for (int kk = 0; kk < 4; ++kk)
            sPostT[warp * KK + kslot * 4 + kk] = csum[kk];   // per-warp cs staging
    }

    // ---- reduce 4 point-replicas of sacc/qacc via smem (sRed spans sX0+sX1) ----
    const int NS = 2 * KK * DD;   // 2048
    float* sRed = sX0;            // 4*NS = 8192 floats <= 17408
#pragma unroll
    for (int kk = 0; kk < 4; ++kk) {
        int k = kg * 4 + kk;
        float2 a0 = funpack2(sacc[kk][0]), a1 = funpack2(sacc[kk][1]);
        float2 b0 = funpack2(qacc[kk][0]), b1 = funpack2(qacc[kk][1]);
        *(float4*)(sRed + rep * NS + k * DD + dg * 4)           = make_float4(a0.x, a0.y, a1.x, a1.y);
        *(float4*)(sRed + rep * NS + KK * DD + k * DD + dg * 4) = make_float4(b0.x, b0.y, b1.x, b1.y);
    }
    __syncthreads();

    float* dst = g_part[iter & 1] + ((size_t)(b * SCH + bid)) * SLOTS;
    for (int i = tid; i < NS; i += NTH)
        dst[i] = (sRed[i] + sRed[NS + i]) + (sRed[2 * NS + i] + sRed[3 * NS + i]);
    if (tid < KK) {
        float v = 0.f;
#pragma unroll
        for (int w = 0; w < 8; ++w) v += sPostT[w * KK + tid];
        dst[NS + tid] = v;
    }
}

// ---------------- Final (flat 444 grid, 3 CTAs/SM): prologue params + logits -> sigmoid ----------------
// SMEM: sAB[2064] | sC[16] | sX[128*68]
__global__ void __launch_bounds__(NTH, 3)
k_final(const float* __restrict__ data, const float* __restrict__ scale,
        const float* __restrict__ bias, float* __restrict__ out) {
    extern __shared__ float sm[];
    float* sAB = sm;
    float* sC  = sm + ABSZ;
    float* sX  = sm + ABSZ + 16;

    const int tid   = threadIdx.x;
    const int lane  = tid & 31;
    const int warp  = tid >> 5;
    const int pslot = lane & 7;
    const int kslot = lane >> 3;

    // flat cta -> (batch, bid): batches 0-3 get 56 CTAs, 4-7 get 55
    int id = blockIdx.x, b, bid, schb;
    if (id < 224) { b = id / 56;             bid = id - b * 56;               schb = 56; }
    else          { b = 4 + (id - 224) / 55; bid = (id - 224) - (b - 4) * 55; schb = 55; }

    const int nsub = (SUBT - 1 - bid) / schb + 1;
    const float* xb = data + (size_t)b * NN * DD;
    const uint32_t uX = s2u(sX);

    // prologue: reduce final partials + rebuild params (sX as scratch, pre-staging)
    reduce_partials(g_part[(ITERS - 1) & 1] + (size_t)b * SCH * SLOTS, sX, tid);
    __syncthreads();
    rebuild_params_smem(tid, sX, sAB, sC, 0, 0);
    __syncthreads();

    const float sc = scale[0], bs = bias[0];

    for (int j = 0; j < nsub; ++j) {
        const int st = bid + j * schb;
        stage(uX, xb + (size_t)st * ST * DD, tid);
        cp_commit();
        cp_wait<0>();
        __syncthreads();

        unsigned long long acc[2][4];
        logits_tile2(sX + (warp * 16 + pslot) * XSTRIDE, sAB + kslot * ABSTR, acc);

#pragma unroll
        for (int pt = 0; pt < 2; ++pt) {
            float o[4];
#pragma unroll
            for (int kk = 0; kk < 4; ++kk) {
                float2 f = funpack2(acc[pt][kk]);
                float z = (sC[kslot * 4 + kk] + f.x + f.y) * sc + bs;
                float e = __expf(-fabsf(z));
                float q = e / (1.f + e);
                o[kk] = (z >= 0.f) ? (1.f - q) : q;
            }
            int p = warp * 16 + pslot + pt * 8;
            float* og = out + ((size_t)b * NN + (size_t)st * ST + p) * KK + kslot * 4;
            *(float4*)og = make_float4(o[0], o[1], o[2], o[3]);
        }
        __syncthreads();   // sX reused as stage target next iteration
    }
}

// ---------------- host launcher (graph-capturable) ----------------
extern "C" void kernel_launch(void* const* d_in, const int* in_sizes, int n_in,
                              void* d_out, int out_size) {
    const float* data  = (const float*)d_in[0];
    const float* means = (const float*)d_in[1];
    const float* scale = (const float*)d_in[2];
    const float* bias  = (const float*)d_in[3];
    float* out = (float*)d_out;

    const int smem_e = (ABSZ + 16 + 2 * ST * XSTRIDE + ST * PSTR) * 4;   // 88192
    const int smem_f = (ABSZ + 16 + ST * XSTRIDE) * 4;                   // 43136
    cudaFuncSetAttribute(k_estep, cudaFuncAttributeMaxDynamicSharedMemorySize, smem_e);
    cudaFuncSetAttribute(k_final, cudaFuncAttributeMaxDynamicSharedMemorySize, smem_f);

    dim3 ge(SCH, BB);                           // 296 CTAs = one full resident wave at 2/SM

    for (int i = 0; i < ITERS; ++i)
        k_estep<<<ge, NTH, smem_e>>>(data, means, i);   // params rebuilt in prologue
    k_final<<<FGRID, NTH, smem_f>>>(data, scale, bias, out);
}

// round 15
// speedup vs baseline: 1.1493x; 1.0208x over previous
#include <cuda_runtime.h>
#include <cstdint>

#define BB 8
#define NN 102400          // points per batch
#define DD 64
#define KK 16
#define ITERS 5
#define ST 128             // points per subtile
#define SUBT (NN/ST)       // 800 subtiles per batch
#define SCH 37             // estep CTAs per batch; 37*8 = 296 = 2*148 -> one wave at 2/SM
#define FGRID 444          // k_final: 3*148 -> one wave at 3/SM
#define SLOTS (2*KK*DD + KK)   // 2064
#define SLOT4 (SLOTS/4)        // 516
#define NTH 256

#define XSTRIDE 68         // padded row stride (floats) for sX (4-bank skew per row)
#define PSTR 20            // padded row stride for posteriors (sPostT: 2560 >= SLOTS)
#define ABSTR 516          // AB block stride per kslot (floats): 4-bank skew, conflict-free
#define ABSZ (4*ABSTR)     // 2064 floats

// ---------------- device scratch ----------------
__device__ float g_part[2][(size_t)BB*SCH*SLOTS];   // parity double-buffered partials

// ---------------- packed f32x2 helpers ----------------
__device__ __forceinline__ unsigned long long f2fma(unsigned long long a, unsigned long long b, unsigned long long c) {
    unsigned long long d;
    asm("fma.rn.f32x2 %0, %1, %2, %3;" : "=l"(d) : "l"(a), "l"(b), "l"(c));
    return d;
}
__device__ __forceinline__ unsigned long long f2mul(unsigned long long a, unsigned long long b) {
    unsigned long long d;
    asm("mul.rn.f32x2 %0, %1, %2;" : "=l"(d) : "l"(a), "l"(b));
    return d;
}
__device__ __forceinline__ unsigned long long fpack2(float lo, float hi) {
    unsigned long long r;
    asm("mov.b64 %0, {%1, %2};" : "=l"(r) : "f"(lo), "f"(hi));
    return r;
}
__device__ __forceinline__ float2 funpack2(unsigned long long v) {
    float2 f;
    asm("mov.b64 {%0, %1}, %2;" : "=f"(f.x), "=f"(f.y) : "l"(v));
    return f;
}

// ---------------- cp.async ----------------
__device__ __forceinline__ void cp16(uint32_t saddr, const void* g) {
    asm volatile("cp.async.ca.shared.global [%0], [%1], 16;" :: "r"(saddr), "l"(g));
}
__device__ __forceinline__ void cp_commit() { asm volatile("cp.async.commit_group;"); }
template<int N> __device__ __forceinline__ void cp_wait() {
    asm volatile("cp.async.wait_group %0;" :: "n"(N));
}
__device__ __forceinline__ uint32_t s2u(const void* p) {
    return (uint32_t)__cvta_generic_to_shared(p);
}

// stage ST=128 points (2048 float4) into padded smem buffer
__device__ __forceinline__ void stage(uint32_t sbuf, const float* __restrict__ src, int tid) {
#pragma unroll
    for (int r = 0; r < 8; ++r) {
        int i = tid + r * NTH;               // 0..2047
        int p = i >> 4, j = i & 15;
        cp16(sbuf + (uint32_t)(p * 17 + j) * 16, src + (size_t)i * 4);
    }
}

// rebuild params from reduced stats (smem) or init means, into skewed smem AB + C
// layout: cluster k at (k>>2)*ABSTR + (k&3)*128, inner per-dg {A01,B01,A23,B23}
__device__ __forceinline__ void rebuild_params_smem(int tid, const float* acc,
                                                    float* sAB, float* sC,
                                                    const float* mrow, int init) {
    const int k = tid >> 4, dg = tid & 15;
    float cs = 0.f, pi;
    if (init) {
        pi = 1.0f / KK;
    } else {
        cs = acc[2 * KK * DD + k];
        float csumall = 0.f;
#pragma unroll
        for (int j = 0; j < KK; ++j) csumall += acc[2 * KK * DD + j];
        pi = cs / csumall;
    }

    float plog = 0.f, pmmi = 0.f;
    float A[4], Bc[4];
#pragma unroll
    for (int t = 0; t < 4; ++t) {
        int d = dg * 4 + t;
        float m, var;
        if (init) {
            m = mrow[k * DD + d];
            var = 1.0f;                                     // COV_INIT
        } else {
            float sx  = acc[k * DD + d];
            float sx2 = acc[KK * DD + k * DD + d];
            m   = sx / (cs + 1e-7f);
            var = sx2 - 2.0f * m * sx + m * m * cs + 1e-6f;
        }
        float inv = 1.0f / (var + 1e-6f);
        plog += logf(6.283185307179586f * var);
        pmmi += m * m * inv;
        A[t]  = m * inv;
        Bc[t] = -0.5f * inv;
    }

    float* abk = sAB + (k >> 2) * ABSTR + (k & 3) * 128;
    *(float4*)(abk + dg * 8)     = make_float4(A[0], A[1], Bc[0], Bc[1]);
    *(float4*)(abk + dg * 8 + 4) = make_float4(A[2], A[3], Bc[2], Bc[3]);

#pragma unroll
    for (int o = 8; o >= 1; o >>= 1) {
        plog += __shfl_xor_sync(0xffffffffu, plog, o);
        pmmi += __shfl_xor_sync(0xffffffffu, pmmi, o);
    }
    if (dg == 0) sC[k] = logf(pi) - 0.5f * plog - 0.5f * pmmi;
}

// vectorized prologue reduction: sum 37 per-CTA partials into smem scratch
__device__ __forceinline__ void reduce_partials(const float* __restrict__ base,
                                                float* __restrict__ accs, int tid) {
    for (int s = tid; s < SLOT4; s += NTH) {
        float4 v = make_float4(0.f, 0.f, 0.f, 0.f);
#pragma unroll 4
        for (int c = 0; c < SCH; ++c) {
            float4 t = *(const float4*)(base + (size_t)c * SLOTS + s * 4);
            v.x += t.x; v.y += t.y; v.z += t.z; v.w += t.w;
        }
        *(float4*)(accs + s * 4) = v;
    }
}

// Register-tiled logits: thread computes 2 points x 4 clusters.
__device__ __forceinline__ void logits_tile2(const float* __restrict__ xrow0,   // point p0; p1 = p0 + 8 rows
                                             const float* __restrict__ abk,    // sAB + kslot*ABSTR
                                             unsigned long long acc[2][4]) {
#pragma unroll
    for (int pt = 0; pt < 2; ++pt)
#pragma unroll
        for (int kk = 0; kk < 4; ++kk) acc[pt][kk] = 0ull;

    const float* xrow1 = xrow0 + 8 * XSTRIDE;
#pragma unroll
    for (int it = 0; it < 16; ++it) {
        ulonglong2 x0 = *(const ulonglong2*)(xrow0 + it * 4);
        ulonglong2 x1 = *(const ulonglong2*)(xrow1 + it * 4);
#pragma unroll
        for (int kk = 0; kk < 4; ++kk) {
            ulonglong2 ab0 = *(const ulonglong2*)(abk + kk * 128 + it * 8);      // {A01,B01}
            ulonglong2 ab1 = *(const ulonglong2*)(abk + kk * 128 + it * 8 + 4);  // {A23,B23}
            unsigned long long u;
            u = f2fma(x0.x, ab0.y, ab0.x); acc[0][kk] = f2fma(x0.x, u, acc[0][kk]);
            u = f2fma(x0.y, ab1.y, ab1.x); acc[0][kk] = f2fma(x0.y, u, acc[0][kk]);
            u = f2fma(x1.x, ab0.y, ab0.x); acc[1][kk] = f2fma(x1.x, u, acc[1][kk]);
            u = f2fma(x1.y, ab1.y, ab1.x); acc[1][kk] = f2fma(x1.y, u, acc[1][kk]);
        }
    }
}

// ---------------- E-step (persistent CTA; 2 barriers per subtile) ----------------
// SMEM (floats): sAB[2064] | sC[16] | sX0[128*68] | sX1[128*68] | sPostT[128*20]
__global__ void __launch_bounds__(NTH, 2)
k_estep(const float* __restrict__ data, const float* __restrict__ means, int iter) {
    extern __shared__ float sm[];
    float* sAB    = sm;
    float* sC     = sm + ABSZ;
    float* sX0    = sm + ABSZ + 16;
    float* sX1    = sX0 + ST * XSTRIDE;
    float* sPostT = sX1 + ST * XSTRIDE;

    const int tid   = threadIdx.x;
    const int lane  = tid & 31;
    const int warp  = tid >> 5;
    const int pslot = lane & 7;
    const int kslot = lane >> 3;
    const int bid   = blockIdx.x;       // 0..36
    const int b     = blockIdx.y;

    // phase-B mapping: clusters kg*4..+3, dims dg*4..+3, points n = 4i+rep
    const int kg  = tid >> 6;
    const int rep = (tid >> 4) & 3;
    const int dg  = tid & 15;

    const int nsub = (SUBT - 1 - bid) / SCH + 1;    // 22 or 21
    const float* xb = data + (size_t)b * NN * DD;
    const uint32_t uX0 = s2u(sX0), uX1 = s2u(sX1);

    // prologue: prefetch subtile bid; reduce prev partials + rebuild params (overlapped)
    stage(uX0, xb + (size_t)bid * ST * DD, tid);
    cp_commit();
    if (iter == 0) {
        rebuild_params_smem(tid, 0, sAB, sC, means + (size_t)b * KK * DD, 1);
    } else {
        reduce_partials(g_part[(iter - 1) & 1] + (size_t)b * SCH * SLOTS, sPostT, tid);
        __syncthreads();
        rebuild_params_smem(tid, sPostT, sAB, sC, 0, 0);
    }

    // persistent accumulators (whole CTA workload)
    unsigned long long sacc[4][2], qacc[4][2];
    float csum[4];
#pragma unroll
    for (int kk = 0; kk < 4; ++kk) {
        sacc[kk][0] = sacc[kk][1] = 0ull;
        qacc[kk][0] = qacc[kk][1] = 0ull;
        csum[kk] = 0.f;
    }

    for (int j = 0; j < nsub; ++j) {
        const float* sX = (j & 1) ? sX1 : sX0;
        cp_wait<0>();
        __syncthreads();    // #1: x[j] staged (all warps); phase B(j-1) done (all warps)
        // prefetch next subtile AFTER the barrier: only buffer (j+1)&1 is written while
        // all concurrent warps read buffer j&1 -> no end-of-loop barrier needed.
        if (j + 1 < nsub) {
            stage((j & 1) ? uX0 : uX1, xb + (size_t)(bid + (j + 1) * SCH) * ST * DD, tid);
            cp_commit();
        }

        // ---- phase A: logits + softmax (2 points x 4 clusters per thread) ----
        unsigned long long acc[2][4];
        logits_tile2(sX + (warp * 16 + pslot) * XSTRIDE, sAB + kslot * ABSTR, acc);

#pragma unroll
        for (int pt = 0; pt < 2; ++pt) {
            float l[4];
#pragma unroll
            for (int kk = 0; kk < 4; ++kk) {
                float2 f = funpack2(acc[pt][kk]);
                l[kk] = sC[kslot * 4 + kk] + f.x + f.y;
            }
            float mx = fmaxf(fmaxf(l[0], l[1]), fmaxf(l[2], l[3]));
            mx = fmaxf(mx, __shfl_xor_sync(0xffffffffu, mx, 8));
            mx = fmaxf(mx, __shfl_xor_sync(0xffffffffu, mx, 16));
            float e0 = __expf(l[0] - mx), e1 = __expf(l[1] - mx);
            float e2 = __expf(l[2] - mx), e3 = __expf(l[3] - mx);
            float ssum = (e0 + e1) + (e2 + e3);
            ssum += __shfl_xor_sync(0xffffffffu, ssum, 8);
            ssum += __shfl_xor_sync(0xffffffffu, ssum, 16);
            float inv = 1.f / ssum;
            e0 *= inv; e1 *= inv; e2 *= inv; e3 *= inv;
            csum[0] += e0; csum[1] += e1; csum[2] += e2; csum[3] += e3;
            int p = warp * 16 + pslot + pt * 8;
            *(float4*)(sPostT + p * PSTR + kslot * 4) = make_float4(e0, e1, e2, e3);
        }
        __syncthreads();    // #2: posts ready for phase B

        // ---- phase B: accumulate sx, sx2 (4k x 4d tile, pointer-increment addressing) ----
        const float* pp = sPostT + rep * PSTR + kg * 4;
        const float* xp = sX + rep * XSTRIDE + dg * 4;
#pragma unroll 8
        for (int i = 0; i < ST / 4; ++i) {
            float4 pv = *(const float4*)pp;
            ulonglong2 xv = *(const ulonglong2*)xp;
            pp += 4 * PSTR;
            xp += 4 * XSTRIDE;
            unsigned long long x2a = f2mul(xv.x, xv.x);
            unsigned long long x2b = f2mul(xv.y, xv.y);
#pragma unroll
            for (int kk = 0; kk < 4; ++kk) {
                float pp0 = (&pv.x)[kk];
                unsigned long long pb = fpack2(pp0, pp0);
                sacc[kk][0] = f2fma(pb, xv.x, sacc[kk][0]);
                sacc[kk][1] = f2fma(pb, xv.y, sacc[kk][1]);
                qacc[kk][0] = f2fma(pb, x2a, qacc[kk][0]);
                qacc[kk][1] = f2fma(pb, x2b, qacc[kk][1]);
            }
        }
        // no end-of-loop barrier: barrier #1 of next iteration orders phase B before
        // the next prefetch into this buffer (2 iterations away).
    }
    __syncthreads();   // protect sX/sPostT reuse in the epilogue below

    // ---- csum: reduce over the 8 pslot lanes of each kslot group ----
#pragma unroll
    for (int o = 1; o <= 4; o <<= 1) {
#pragma unroll
        for (int kk = 0; kk < 4; ++kk)
            csum[kk] += __shfl_xor_sync(0xffffffffu, csum[kk], o);
    }
    if (pslot == 0) {
#pragma unroll
        for (int kk = 0; kk < 4; ++kk)
            sPostT[warp * KK + kslot * 4 + kk] = csum[kk];   // per-warp cs staging
    }

    // ---- reduce 4 point-replicas of sacc/qacc via smem (sRed spans sX0+sX1) ----
    const int NS = 2 * KK * DD;   // 2048
    float* sRed = sX0;            // 4*NS = 8192 floats <= 17408
#pragma unroll
    for (int kk = 0; kk < 4; ++kk) {
        int k = kg * 4 + kk;
        float2 a0 = funpack2(sacc[kk][0]), a1 = funpack2(sacc[kk][1]);
        float2 b0 = funpack2(qacc[kk][0]), b1 = funpack2(qacc[kk][1]);
        *(float4*)(sRed + rep * NS + k * DD + dg * 4)           = make_float4(a0.x, a0.y, a1.x, a1.y);
        *(float4*)(sRed + rep * NS + KK * DD + k * DD + dg * 4) = make_float4(b0.x, b0.y, b1.x, b1.y);
    }
    __syncthreads();

    float* dst = g_part[iter & 1] + ((size_t)(b * SCH + bid)) * SLOTS;
    for (int i = tid; i < NS; i += NTH)
        dst[i] = (sRed[i] + sRed[NS + i]) + (sRed[2 * NS + i] + sRed[3 * NS + i]);
    if (tid < KK) {
        float v = 0.f;
#pragma unroll
        for (int w = 0; w < 8; ++w) v += sPostT[w * KK + tid];
        dst[NS + tid] = v;
    }
}

// ---------------- Final (flat 444 grid, 3 CTAs/SM): prologue params + logits -> sigmoid ----------------
// SMEM: sAB[2064] | sC[16] | sX[128*68]
__global__ void __launch_bounds__(NTH, 3)
k_final(const float* __restrict__ data, const float* __restrict__ scale,
        const float* __restrict__ bias, float* __restrict__ out) {
    extern __shared__ float sm[];
    float* sAB = sm;
    float* sC  = sm + ABSZ;
    float* sX  = sm + ABSZ + 16;

    const int tid   = threadIdx.x;
    const int lane  = tid & 31;
    const int warp  = tid >> 5;
    const int pslot = lane & 7;
    const int kslot = lane >> 3;

    // flat cta -> (batch, bid): batches 0-3 get 56 CTAs, 4-7 get 55
    int id = blockIdx.x, b, bid, schb;
    if (id < 224) { b = id / 56;             bid = id - b * 56;               schb = 56; }
    else          { b = 4 + (id - 224) / 55; bid = (id - 224) - (b - 4) * 55; schb = 55; }

    const int nsub = (SUBT - 1 - bid) / schb + 1;
    const float* xb = data + (size_t)b * NN * DD;
    const uint32_t uX = s2u(sX);

    // prologue: reduce final partials + rebuild params (sX as scratch, pre-staging)
    reduce_partials(g_part[(ITERS - 1) & 1] + (size_t)b * SCH * SLOTS, sX, tid);
    __syncthreads();
    rebuild_params_smem(tid, sX, sAB, sC, 0, 0);
    __syncthreads();

    const float sc = scale[0], bs = bias[0];

    for (int j = 0; j < nsub; ++j) {
        const int st = bid + j * schb;
        stage(uX, xb + (size_t)st * ST * DD, tid);
        cp_commit();
        cp_wait<0>();
        __syncthreads();

        unsigned long long acc[2][4];
        logits_tile2(sX + (warp * 16 + pslot) * XSTRIDE, sAB + kslot * ABSTR, acc);

#pragma unroll
        for (int pt = 0; pt < 2; ++pt) {
            float o[4];
#pragma unroll
            for (int kk = 0; kk < 4; ++kk) {
                float2 f = funpack2(acc[pt][kk]);
                float z = (sC[kslot * 4 + kk] + f.x + f.y) * sc + bs;
                float e = __expf(-fabsf(z));
                float q = e / (1.f + e);
                o[kk] = (z >= 0.f) ? (1.f - q) : q;
            }
            int p = warp * 16 + pslot + pt * 8;
            float* og = out + ((size_t)b * NN + (size_t)st * ST + p) * KK + kslot * 4;
            *(float4*)og = make_float4(o[0], o[1], o[2], o[3]);
        }
        __syncthreads();   // sX reused as stage target next iteration
    }
}

// ---------------- host launcher (graph-capturable) ----------------
extern "C" void kernel_launch(void* const* d_in, const int* in_sizes, int n_in,
                              void* d_out, int out_size) {
    const float* data  = (const float*)d_in[0];
    const float* means = (const float*)d_in[1];
    const float* scale = (const float*)d_in[2];
    const float* bias  = (const float*)d_in[3];
    float* out = (float*)d_out;

    const int smem_e = (ABSZ + 16 + 2 * ST * XSTRIDE + ST * PSTR) * 4;   // 88192
    const int smem_f = (ABSZ + 16 + ST * XSTRIDE) * 4;                   // 43136
    cudaFuncSetAttribute(k_estep, cudaFuncAttributeMaxDynamicSharedMemorySize, smem_e);
    cudaFuncSetAttribute(k_final, cudaFuncAttributeMaxDynamicSharedMemorySize, smem_f);

    dim3 ge(SCH, BB);                           // 296 CTAs = one full resident wave at 2/SM

    for (int i = 0; i < ITERS; ++i)
        k_estep<<<ge, NTH, smem_e>>>(data, means, i);   // params rebuilt in prologue
    k_final<<<FGRID, NTH, smem_f>>>(data, scale, bias, out);
}

// round 16
// speedup vs baseline: 1.1903x; 1.0357x over previous
#include <cuda_runtime.h>
#include <cstdint>

#define BB 8
#define NN 102400          // points per batch
#define DD 64
#define KK 16
#define ITERS 5
#define ST 128             // points per subtile
#define SUBT (NN/ST)       // 800 subtiles per batch
#define SCH 37             // estep CTAs per batch; 37*8 = 296 = 2*148 -> one wave at 2/SM
#define FGRID 444          // k_final: 3*148 -> one wave at 3/SM
#define SLOTS (2*KK*DD + KK)   // 2064
#define SLOT4 (SLOTS/4)        // 516
#define NTH 256

#define XSTRIDE 68         // padded row stride (floats) for sX (4-bank skew per row)
#define PSTR 20            // padded row stride for posteriors (sPostT: 2560 >= SLOTS)
#define ABSTR 516          // AB block stride per kslot (floats): 4-bank skew, conflict-free
#define ABSZ (4*ABSTR)     // 2064 floats

// ---------------- device scratch ----------------
__device__ float g_part[2][(size_t)BB*SCH*SLOTS];   // parity double-buffered partials

// ---------------- packed f32x2 helpers ----------------
__device__ __forceinline__ unsigned long long f2fma(unsigned long long a, unsigned long long b, unsigned long long c) {
    unsigned long long d;
    asm("fma.rn.f32x2 %0, %1, %2, %3;" : "=l"(d) : "l"(a), "l"(b), "l"(c));
    return d;
}
__device__ __forceinline__ unsigned long long f2mul(unsigned long long a, unsigned long long b) {
    unsigned long long d;
    asm("mul.rn.f32x2 %0, %1, %2;" : "=l"(d) : "l"(a), "l"(b));
    return d;
}
__device__ __forceinline__ unsigned long long fpack2(float lo, float hi) {
    unsigned long long r;
    asm("mov.b64 %0, {%1, %2};" : "=l"(r) : "f"(lo), "f"(hi));
    return r;
}
__device__ __forceinline__ float2 funpack2(unsigned long long v) {
    float2 f;
    asm("mov.b64 {%0, %1}, %2;" : "=f"(f.x), "=f"(f.y) : "l"(v));
    return f;
}

// ---------------- cp.async ----------------
__device__ __forceinline__ void cp16(uint32_t saddr, const void* g) {
    asm volatile("cp.async.ca.shared.global [%0], [%1], 16;" :: "r"(saddr), "l"(g));
}
__device__ __forceinline__ void cp_commit() { asm volatile("cp.async.commit_group;"); }
template<int N> __device__ __forceinline__ void cp_wait() {
    asm volatile("cp.async.wait_group %0;" :: "n"(N));
}
__device__ __forceinline__ uint32_t s2u(const void* p) {
    return (uint32_t)__cvta_generic_to_shared(p);
}
__device__ __forceinline__ void pair_bar(int id) {
    asm volatile("bar.sync %0, 64;" :: "r"(id) : "memory");
}

// stage ST=128 points (2048 float4) into padded smem buffer (CTA-wide, k_final)
__device__ __forceinline__ void stage(uint32_t sbuf, const float* __restrict__ src, int tid) {
#pragma unroll
    for (int r = 0; r < 8; ++r) {
        int i = tid + r * NTH;               // 0..2047
        int p = i >> 4, j = i & 15;
        cp16(sbuf + (uint32_t)(p * 17 + j) * 16, src + (size_t)i * 4);
    }
}

// stage a 32-point pair slice (512 float4) into rows [wp*32, wp*32+32) of sbuf
__device__ __forceinline__ void stage_pair(uint32_t sbuf, const float* __restrict__ src,
                                           int wp, int t2) {
#pragma unroll
    for (int r = 0; r < 8; ++r) {
        int i = t2 + r * 64;                 // 0..511
        int p = i >> 4, j = i & 15;          // local point 0..31
        cp16(sbuf + (uint32_t)((wp * 32 + p) * 17 + j) * 16, src + (size_t)i * 4);
    }
}

// rebuild params from reduced stats (smem) or init means, into skewed smem AB + C
// layout: cluster k at (k>>2)*ABSTR + (k&3)*128, inner per-dg {A01,B01,A23,B23}
__device__ __forceinline__ void rebuild_params_smem(int tid, const float* acc,
                                                    float* sAB, float* sC,
                                                    const float* mrow, int init) {
    const int k = tid >> 4, dg = tid & 15;
    float cs = 0.f, pi;
    if (init) {
        pi = 1.0f / KK;
    } else {
        cs = acc[2 * KK * DD + k];
        float csumall = 0.f;
#pragma unroll
        for (int j = 0; j < KK; ++j) csumall += acc[2 * KK * DD + j];
        pi = cs / csumall;
    }

    float plog = 0.f, pmmi = 0.f;
    float A[4], Bc[4];
#pragma unroll
    for (int t = 0; t < 4; ++t) {
        int d = dg * 4 + t;
        float m, var;
        if (init) {
            m = mrow[k * DD + d];
            var = 1.0f;                                     // COV_INIT
        } else {
            float sx  = acc[k * DD + d];
            float sx2 = acc[KK * DD + k * DD + d];
            m   = sx / (cs + 1e-7f);
            var = sx2 - 2.0f * m * sx + m * m * cs + 1e-6f;
        }
        float inv = 1.0f / (var + 1e-6f);
        plog += logf(6.283185307179586f * var);
        pmmi += m * m * inv;
        A[t]  = m * inv;
        Bc[t] = -0.5f * inv;
    }

    float* abk = sAB + (k >> 2) * ABSTR + (k & 3) * 128;
    *(float4*)(abk + dg * 8)     = make_float4(A[0], A[1], Bc[0], Bc[1]);
    *(float4*)(abk + dg * 8 + 4) = make_float4(A[2], A[3], Bc[2], Bc[3]);

#pragma unroll
    for (int o = 8; o >= 1; o >>= 1) {
        plog += __shfl_xor_sync(0xffffffffu, plog, o);
        pmmi += __shfl_xor_sync(0xffffffffu, pmmi, o);
    }
    if (dg == 0) sC[k] = logf(pi) - 0.5f * plog - 0.5f * pmmi;
}

// vectorized prologue reduction: sum 37 per-CTA partials into smem scratch
__device__ __forceinline__ void reduce_partials(const float* __restrict__ base,
                                                float* __restrict__ accs, int tid) {
    for (int s = tid; s < SLOT4; s += NTH) {
        float4 v = make_float4(0.f, 0.f, 0.f, 0.f);
#pragma unroll 4
        for (int c = 0; c < SCH; ++c) {
            float4 t = *(const float4*)(base + (size_t)c * SLOTS + s * 4);
            v.x += t.x; v.y += t.y; v.z += t.z; v.w += t.w;
        }
        *(float4*)(accs + s * 4) = v;
    }
}

// Register-tiled logits: thread computes 2 points x 4 clusters (warp-local 16 points).
__device__ __forceinline__ void logits_tile2(const float* __restrict__ xrow0,   // point p0; p1 = p0 + 8 rows
                                             const float* __restrict__ abk,    // sAB + kslot*ABSTR
                                             unsigned long long acc[2][4]) {
#pragma unroll
    for (int pt = 0; pt < 2; ++pt)
#pragma unroll
        for (int kk = 0; kk < 4; ++kk) acc[pt][kk] = 0ull;

    const float* xrow1 = xrow0 + 8 * XSTRIDE;
#pragma unroll
    for (int it = 0; it < 16; ++it) {
        ulonglong2 x0 = *(const ulonglong2*)(xrow0 + it * 4);
        ulonglong2 x1 = *(const ulonglong2*)(xrow1 + it * 4);
#pragma unroll
        for (int kk = 0; kk < 4; ++kk) {
            ulonglong2 ab0 = *(const ulonglong2*)(abk + kk * 128 + it * 8);      // {A01,B01}
            ulonglong2 ab1 = *(const ulonglong2*)(abk + kk * 128 + it * 8 + 4);  // {A23,B23}
            unsigned long long u;
            u = f2fma(x0.x, ab0.y, ab0.x); acc[0][kk] = f2fma(x0.x, u, acc[0][kk]);
            u = f2fma(x0.y, ab1.y, ab1.x); acc[0][kk] = f2fma(x0.y, u, acc[0][kk]);
            u = f2fma(x1.x, ab0.y, ab0.x); acc[1][kk] = f2fma(x1.x, u, acc[1][kk]);
            u = f2fma(x1.y, ab1.y, ab1.x); acc[1][kk] = f2fma(x1.y, u, acc[1][kk]);
        }
    }
}

// ---------------- E-step: 4 independent warp-pair pipelines per CTA ----------------
// SMEM (floats): sAB[2064] | sC[16] | sX0[128*68] | sX1[128*68] | sPostT[128*20]
__global__ void __launch_bounds__(NTH, 2)
k_estep(const float* __restrict__ data, const float* __restrict__ means, int iter) {
    extern __shared__ float sm[];
    float* sAB    = sm;
    float* sC     = sm + ABSZ;
    float* sX0    = sm + ABSZ + 16;
    float* sX1    = sX0 + ST * XSTRIDE;
    float* sPostT = sX1 + ST * XSTRIDE;

    const int tid   = threadIdx.x;
    const int lane  = tid & 31;
    const int warp  = tid >> 5;
    const int pslot = lane & 7;
    const int kslot = lane >> 3;
    const int bid   = blockIdx.x;       // 0..36
    const int b     = blockIdx.y;

    // pair mapping
    const int wp = warp >> 1;                    // 0..3
    const int t2 = ((warp & 1) << 5) | lane;     // 0..63 within pair
    const int kg = t2 >> 4;                      // 0..3 (4 clusters each)
    const int dg = t2 & 15;                      // 0..15 (4 dims each)
    const int barid = wp + 1;                    // named barrier ids 1..4

    const int nsub = (SUBT - 1 - bid) / SCH + 1;    // 22 or 21
    const float* xb = data + (size_t)b * NN * DD;
    const uint32_t uX0 = s2u(sX0), uX1 = s2u(sX1);

    // prologue: pair-prefetch subtile bid slice; reduce prev partials + rebuild params
    stage_pair(uX0, xb + ((size_t)bid * ST + wp * 32) * DD, wp, t2);
    cp_commit();
    if (iter == 0) {
        rebuild_params_smem(tid, 0, sAB, sC, means + (size_t)b * KK * DD, 1);
    } else {
        reduce_partials(g_part[(iter - 1) & 1] + (size_t)b * SCH * SLOTS, sPostT, tid);
        __syncthreads();
        rebuild_params_smem(tid, sPostT, sAB, sC, 0, 0);
    }
    __syncthreads();   // params visible to all warps before pair pipelines diverge

    // persistent accumulators (whole CTA workload)
    unsigned long long sacc[4][2], qacc[4][2];
    float csum[4];
#pragma unroll
    for (int kk = 0; kk < 4; ++kk) {
        sacc[kk][0] = sacc[kk][1] = 0ull;
        qacc[kk][0] = qacc[kk][1] = 0ull;
        csum[kk] = 0.f;
    }

    for (int j = 0; j < nsub; ++j) {
        const float* sX = (j & 1) ? sX1 : sX0;
        cp_wait<0>();      // own copies of x(j) complete
        pair_bar(barid);   // barA: pair's x(j) visible; partner done with phase B(j-1)
        // prefetch next subtile's slice (other buffer) - safe: pair reads buffer j&1 only
        if (j + 1 < nsub) {
            stage_pair((j & 1) ? uX0 : uX1,
                       xb + ((size_t)(bid + (j + 1) * SCH) * ST + wp * 32) * DD, wp, t2);
            cp_commit();
        }

        // ---- phase A: logits + softmax (warp-local 16 points) ----
        unsigned long long acc[2][4];
        logits_tile2(sX + (warp * 16 + pslot) * XSTRIDE, sAB + kslot * ABSTR, acc);

#pragma unroll
        for (int pt = 0; pt < 2; ++pt) {
            float l[4];
#pragma unroll
            for (int kk = 0; kk < 4; ++kk) {
                float2 f = funpack2(acc[pt][kk]);
                l[kk] = sC[kslot * 4 + kk] + f.x + f.y;
            }
            float mx = fmaxf(fmaxf(l[0], l[1]), fmaxf(l[2], l[3]));
            mx = fmaxf(mx, __shfl_xor_sync(0xffffffffu, mx, 8));
            mx = fmaxf(mx, __shfl_xor_sync(0xffffffffu, mx, 16));
            float e0 = __expf(l[0] - mx), e1 = __expf(l[1] - mx);
            float e2 = __expf(l[2] - mx), e3 = __expf(l[3] - mx);
            float ssum = (e0 + e1) + (e2 + e3);
            ssum += __shfl_xor_sync(0xffffffffu, ssum, 8);
            ssum += __shfl_xor_sync(0xffffffffu, ssum, 16);
            float inv = 1.f / ssum;
            e0 *= inv; e1 *= inv; e2 *= inv; e3 *= inv;
            csum[0] += e0; csum[1] += e1; csum[2] += e2; csum[3] += e3;
            int p = warp * 16 + pslot + pt * 8;
            *(float4*)(sPostT + p * PSTR + kslot * 4) = make_float4(e0, e1, e2, e3);
        }
        pair_bar(barid);   // barB: pair's posts ready for phase B

        // ---- phase B: accumulate sx, sx2 over the pair's 32 points ----
        const float* pp = sPostT + (wp * 32) * PSTR + kg * 4;
        const float* xp = sX + (wp * 32) * XSTRIDE + dg * 4;
#pragma unroll 8
        for (int i = 0; i < 32; ++i) {
            float4 pv = *(const float4*)pp;
            ulonglong2 xv = *(const ulonglong2*)xp;
            pp += PSTR;
            xp += XSTRIDE;
            unsigned long long x2a = f2mul(xv.x, xv.x);
            unsigned long long x2b = f2mul(xv.y, xv.y);
#pragma unroll
            for (int kk = 0; kk < 4; ++kk) {
                float pp0 = (&pv.x)[kk];
                unsigned long long pb = fpack2(pp0, pp0);
                sacc[kk][0] = f2fma(pb, xv.x, sacc[kk][0]);
                sacc[kk][1] = f2fma(pb, xv.y, sacc[kk][1]);
                qacc[kk][0] = f2fma(pb, x2a, qacc[kk][0]);
                qacc[kk][1] = f2fma(pb, x2b, qacc[kk][1]);
            }
        }
        // no trailing barrier: next iteration's barA orders phase B before buffer reuse
    }
    __syncthreads();   // all pairs done; sX/sPostT reused in epilogue

    // ---- csum: reduce over the 8 pslot lanes of each kslot group ----
#pragma unroll
    for (int o = 1; o <= 4; o <<= 1) {
#pragma unroll
        for (int kk = 0; kk < 4; ++kk)
            csum[kk] += __shfl_xor_sync(0xffffffffu, csum[kk], o);
    }
    if (pslot == 0) {
#pragma unroll
        for (int kk = 0; kk < 4; ++kk)
            sPostT[warp * KK + kslot * 4 + kk] = csum[kk];   // per-warp cs staging
    }

    // ---- reduce 4 pair-replicas of sacc/qacc via smem (sRed spans sX0+sX1) ----
    const int NS = 2 * KK * DD;   // 2048
    float* sRed = sX0;            // 4*NS = 8192 floats <= 17408
#pragma unroll
    for (int kk = 0; kk < 4; ++kk) {
        int k = kg * 4 + kk;
        float2 a0 = funpack2(sacc[kk][0]), a1 = funpack2(sacc[kk][1]);
        float2 b0 = funpack2(qacc[kk][0]), b1 = funpack2(qacc[kk][1]);
        *(float4*)(sRed + wp * NS + k * DD + dg * 4)           = make_float4(a0.x, a0.y, a1.x, a1.y);
        *(float4*)(sRed + wp * NS + KK * DD + k * DD + dg * 4) = make_float4(b0.x, b0.y, b1.x, b1.y);
    }
    __syncthreads();

    float* dst = g_part[iter & 1] + ((size_t)(b * SCH + bid)) * SLOTS;
    for (int i = tid; i < NS; i += NTH)
        dst[i] = (sRed[i] + sRed[NS + i]) + (sRed[2 * NS + i] + sRed[3 * NS + i]);
    if (tid < KK) {
        float v = 0.f;
#pragma unroll
        for (int w = 0; w < 8; ++w) v += sPostT[w * KK + tid];
        dst[NS + tid] = v;
    }
}

// ---------------- Final (flat 444 grid, 3 CTAs/SM): prologue params + logits -> sigmoid ----------------
// SMEM: sAB[2064] | sC[16] | sX[128*68]
__global__ void __launch_bounds__(NTH, 3)
k_final(const float* __restrict__ data, const float* __restrict__ scale,
        const float* __restrict__ bias, float* __restrict__ out) {
    extern __shared__ float sm[];
    float* sAB = sm;
    float* sC  = sm + ABSZ;
    float* sX  = sm + ABSZ + 16;

    const int tid   = threadIdx.x;
    const int lane  = tid & 31;
    const int warp  = tid >> 5;
    const int pslot = lane & 7;
    const int kslot = lane >> 3;

    // flat cta -> (batch, bid): batches 0-3 get 56 CTAs, 4-7 get 55
    int id = blockIdx.x, b, bid, schb;
    if (id < 224) { b = id / 56;             bid = id - b * 56;               schb = 56; }
    else          { b = 4 + (id - 224) / 55; bid = (id - 224) - (b - 4) * 55; schb = 55; }

    const int nsub = (SUBT - 1 - bid) / schb + 1;
    const float* xb = data + (size_t)b * NN * DD;
    const uint32_t uX = s2u(sX);

    // prologue: reduce final partials + rebuild params (sX as scratch, pre-staging)
    reduce_partials(g_part[(ITERS - 1) & 1] + (size_t)b * SCH * SLOTS, sX, tid);
    __syncthreads();
    rebuild_params_smem(tid, sX, sAB, sC, 0, 0);
    __syncthreads();

    const float sc = scale[0], bs = bias[0];

    for (int j = 0; j < nsub; ++j) {
        const int st = bid + j * schb;
        stage(uX, xb + (size_t)st * ST * DD, tid);
        cp_commit();
        cp_wait<0>();
        __syncthreads();

        unsigned long long acc[2][4];
        logits_tile2(sX + (warp * 16 + pslot) * XSTRIDE, sAB + kslot * ABSTR, acc);

#pragma unroll
        for (int pt = 0; pt < 2; ++pt) {
            float o[4];
#pragma unroll
            for (int kk = 0; kk < 4; ++kk) {
                float2 f = funpack2(acc[pt][kk]);
                float z = (sC[kslot * 4 + kk] + f.x + f.y) * sc + bs;
                float e = __expf(-fabsf(z));
                float q = e / (1.f + e);
                o[kk] = (z >= 0.f) ? (1.f - q) : q;
            }
            int p = warp * 16 + pslot + pt * 8;
            float* og = out + ((size_t)b * NN + (size_t)st * ST + p) * KK + kslot * 4;
            *(float4*)og = make_float4(o[0], o[1], o[2], o[3]);
        }
        __syncthreads();   // sX reused as stage target next iteration
    }
}

// ---------------- host launcher (graph-capturable) ----------------
extern "C" void kernel_launch(void* const* d_in, const int* in_sizes, int n_in,
                              void* d_out, int out_size) {
    const float* data  = (const float*)d_in[0];
    const float* means = (const float*)d_in[1];
    const float* scale = (const float*)d_in[2];
    const float* bias  = (const float*)d_in[3];
    float* out = (float*)d_out;

    const int smem_e = (ABSZ + 16 + 2 * ST * XSTRIDE + ST * PSTR) * 4;   // 88192
    const int smem_f = (ABSZ + 16 + ST * XSTRIDE) * 4;                   // 43136
    cudaFuncSetAttribute(k_estep, cudaFuncAttributeMaxDynamicSharedMemorySize, smem_e);
    cudaFuncSetAttribute(k_final, cudaFuncAttributeMaxDynamicSharedMemorySize, smem_f);

    dim3 ge(SCH, BB);                           // 296 CTAs = one full resident wave at 2/SM

    for (int i = 0; i < ITERS; ++i)
        k_estep<<<ge, NTH, smem_e>>>(data, means, i);   // params rebuilt in prologue
    k_final<<<FGRID, NTH, smem_f>>>(data, scale, bias, out);
}